// round 12
// baseline (speedup 1.0000x reference)
#include <cuda_runtime.h>
#include <cuda_bf16.h>
#include <cstdint>

// TensorProductScatter: in-kernel CSR-by-dst + pipelined register-accumulating
// consumer. Differences vs the failed R4 CSR attempt: the consumer processes
// TWO edges per iteration with all loads batched (loop body has no stores, so
// ptxas software-pipelines across iterations), accumulates the 352-float row
// in 11 regs/lane, and writes it once per dst. Removes the 1.13 GB per-edge
// flush L2 traffic and ~420 MB of out-region DRAM RMW that bound R8.

#define MULC 32
#define ROWF 352            // 32 + 96 + 96 + 32 + 96
#define WARPS_PER_BLOCK 8
#define MAX_E 800000
#define MAX_N 50000

__device__ int d_counts[MAX_N];
__device__ int d_offsets[MAX_N + 1];
__device__ int d_wptr[MAX_N];
__device__ int d_perm[MAX_E];

// ---------------- preprocessing ----------------

__global__ void tps_zero_counts(int N) {
    int i = blockIdx.x * blockDim.x + threadIdx.x;
    if (i < N) d_counts[i] = 0;
}

__global__ void tps_hist(const int* __restrict__ edge_dst, int E) {
    int e = blockIdx.x * blockDim.x + threadIdx.x;
    if (e < E) atomicAdd(&d_counts[edge_dst[e]], 1);
}

__global__ __launch_bounds__(1024) void tps_scan(int N) {
    __shared__ int partial[1024];
    const int t = threadIdx.x;
    const int chunk = (N + 1023) / 1024;
    const int start = t * chunk;
    const int end   = min(start + chunk, N);

    int sum = 0;
    for (int i = start; i < end; i++) sum += d_counts[i];
    partial[t] = sum;
    __syncthreads();
    for (int d = 1; d < 1024; d <<= 1) {
        int v = (t >= d) ? partial[t - d] : 0;
        __syncthreads();
        partial[t] += v;
        __syncthreads();
    }
    int run = (t == 0) ? 0 : partial[t - 1];
    for (int i = start; i < end; i++) {
        d_offsets[i] = run;
        d_wptr[i]    = run;
        run += d_counts[i];
    }
    if (end >= N) d_offsets[N] = run;
}

__global__ void tps_fill(const int* __restrict__ edge_dst, int E) {
    int e = blockIdx.x * blockDim.x + threadIdx.x;
    if (e < E) {
        int pos = atomicAdd(&d_wptr[edge_dst[e]], 1);
        d_perm[pos] = e;
    }
}

// ---------------- consumer ----------------

struct Acc {
    float a0;
    float a1x, a1y, a1z;
    float a2x, a2y, a2z;
    float a3;
    float a4x, a4y, a4z;
};

// Loads + tensor product for one edge; pure loads + FMA (reorderable).
__device__ __forceinline__ void acc_edge(int e, int lane,
                                         const float* __restrict__ x,
                                         const float* __restrict__ edge_attr,
                                         const float* __restrict__ edge_weight,
                                         const int*   __restrict__ edge_src,
                                         Acc& A) {
    const int s = __ldg(edge_src + e);
    const float4 a = __ldg(reinterpret_cast<const float4*>(edge_attr) + e);

    const float* xrow = x + (long long)s * (4 * MULC);
    const float xs0 = __ldg(xrow + lane);
    const float x1a = __ldg(xrow + MULC + 3 * lane + 0);
    const float x1b = __ldg(xrow + MULC + 3 * lane + 1);
    const float x1c = __ldg(xrow + MULC + 3 * lane + 2);

    const float* wrow = edge_weight + (long long)e * (5 * MULC);
    const float w0 = __ldcs(wrow + 0 * MULC + lane);
    const float w1 = __ldcs(wrow + 1 * MULC + lane);
    const float w2 = __ldcs(wrow + 2 * MULC + lane);
    const float w3 = __ldcs(wrow + 3 * MULC + lane);
    const float w4 = __ldcs(wrow + 4 * MULC + lane);

    const float INV_SQRT3 = 0.5773502691896258f;
    const float INV_SQRT2 = 0.7071067811865476f;

    A.a0 += w0 * xs0 * a.x;
    const float w1x = w1 * xs0;
    A.a1x += w1x * a.y;  A.a1y += w1x * a.z;  A.a1z += w1x * a.w;
    const float w2a = w2 * a.x;
    A.a2x += w2a * x1a;  A.a2y += w2a * x1b;  A.a2z += w2a * x1c;
    const float dot = x1a * a.y + x1b * a.z + x1c * a.w;
    A.a3 += w3 * dot * INV_SQRT3;
    const float cx = x1b * a.w - x1c * a.z;
    const float cy = x1c * a.y - x1a * a.w;
    const float cz = x1a * a.z - x1b * a.y;
    const float w4s = w4 * INV_SQRT2;
    A.a4x += w4s * cx;  A.a4y += w4s * cy;  A.a4z += w4s * cz;
}

__global__ __launch_bounds__(WARPS_PER_BLOCK * 32)
void tps_csr_kernel(const float* __restrict__ x,
                    const float* __restrict__ edge_attr,
                    const float* __restrict__ edge_weight,
                    const int*   __restrict__ edge_src,
                    float*       __restrict__ out,
                    int N) {
    __shared__ __align__(16) float sm[WARPS_PER_BLOCK][ROWF];

    const int wb   = threadIdx.x >> 5;
    const int lane = threadIdx.x & 31;
    const int d    = blockIdx.x * WARPS_PER_BLOCK + wb;
    if (d >= N) return;

    const int beg = d_offsets[d];
    const int end = d_offsets[d + 1];

    Acc A = {};   // two independent accumulator sets -> 2-edge ILP
    Acc B = {};

    int i = beg;
    for (; i + 1 < end; i += 2) {
        const int eA = __ldg(d_perm + i);
        const int eB = __ldg(d_perm + i + 1);
        acc_edge(eA, lane, x, edge_attr, edge_weight, edge_src, A);
        acc_edge(eB, lane, x, edge_attr, edge_weight, edge_src, B);
    }
    if (i < end) {
        const int eA = __ldg(d_perm + i);
        acc_edge(eA, lane, x, edge_attr, edge_weight, edge_src, A);
    }

    A.a0  += B.a0;
    A.a1x += B.a1x;  A.a1y += B.a1y;  A.a1z += B.a1z;
    A.a2x += B.a2x;  A.a2y += B.a2y;  A.a2z += B.a2z;
    A.a3  += B.a3;
    A.a4x += B.a4x;  A.a4y += B.a4y;  A.a4z += B.a4z;

    // Stage row (stride-3: gcd(3,32)=1 -> conflict-free), store once (no atomics)
    float* r = sm[wb];
    r[lane]                = A.a0;
    r[MULC + 3 * lane + 0] = A.a1x;
    r[MULC + 3 * lane + 1] = A.a1y;
    r[MULC + 3 * lane + 2] = A.a1z;
    r[128  + 3 * lane + 0] = A.a2x;
    r[128  + 3 * lane + 1] = A.a2y;
    r[128  + 3 * lane + 2] = A.a2z;
    r[224  + lane]         = A.a3;
    r[256  + 3 * lane + 0] = A.a4x;
    r[256  + 3 * lane + 1] = A.a4y;
    r[256  + 3 * lane + 2] = A.a4z;
    __syncwarp();

    const float4* rv = reinterpret_cast<const float4*>(r);
    float4* orow = reinterpret_cast<float4*>(out + (long long)d * ROWF);
    #pragma unroll
    for (int c = lane; c < ROWF / 4; c += 32) {
        orow[c] = rv[c];
    }
}

// ---------------- launch ----------------

extern "C" void kernel_launch(void* const* d_in, const int* in_sizes, int n_in,
                              void* d_out, int out_size) {
    const float* x           = (const float*)d_in[0];
    const float* edge_attr   = (const float*)d_in[1];
    const float* edge_weight = (const float*)d_in[2];
    const int*   edge_dst    = (const int*)d_in[3];
    const int*   edge_src    = (const int*)d_in[4];
    float* out = (float*)d_out;

    const int E = in_sizes[3];
    const int N = out_size / ROWF;

    tps_zero_counts<<<(N + 255) / 256, 256>>>(N);
    tps_hist<<<(E + 255) / 256, 256>>>(edge_dst, E);
    tps_scan<<<1, 1024>>>(N);
    tps_fill<<<(E + 255) / 256, 256>>>(edge_dst, E);

    int blocks = (N + WARPS_PER_BLOCK - 1) / WARPS_PER_BLOCK;
    tps_csr_kernel<<<blocks, WARPS_PER_BLOCK * 32>>>(
        x, edge_attr, edge_weight, edge_src, out, N);
}